// round 2
// baseline (speedup 1.0000x reference)
#include <cuda_runtime.h>
#include <cuda_bf16.h>

#define D 128
#define MAX_N 100000

// Scratch: per-node weighted-neighbor sum (D_in space) and in-degree count.
__device__ __align__(128) float g_agg[(size_t)MAX_N * D];
__device__ __align__(128) float g_deg[MAX_N];
__device__ int g_idx_is64;   // 1 if edge_index buffer is int64, 0 if int32

// ---------------------------------------------------------------------------
// Kernel 0: probe edge_index dtype. If the buffer holds int64 values < 2^31,
// every odd int32 word (little-endian high half) is zero. If it holds int32
// node ids, odd words are random indices (~0 chance all 128 are zero).
// ---------------------------------------------------------------------------
__global__ void probe_kernel(const int* __restrict__ e32, int n_words) {
    if (threadIdx.x == 0) {
        int any = 0;
        for (int i = 1; i < 256 && i < n_words; i += 2) any |= e32[i];
        g_idx_is64 = (any == 0) ? 1 : 0;
    }
}

// ---------------------------------------------------------------------------
// Kernel 1: zero the scratch accumulators (graph replays reuse them).
// ---------------------------------------------------------------------------
__global__ void zero_kernel(int n_nodes) {
    size_t total4 = (size_t)n_nodes * D / 4;
    size_t idx = (size_t)blockIdx.x * blockDim.x + threadIdx.x;
    size_t stride = (size_t)gridDim.x * blockDim.x;
    float4 z = make_float4(0.f, 0.f, 0.f, 0.f);
    float4* p = reinterpret_cast<float4*>(g_agg);
    for (size_t i = idx; i < total4; i += stride) p[i] = z;
    for (size_t i = idx; i < (size_t)n_nodes; i += stride) g_deg[i] = 0.f;
}

// ---------------------------------------------------------------------------
// Kernel 2: edge scatter in D_in space. One warp per edge:
//   g_agg[row] += w * x[col]   (128 floats = 1 float4 per lane, vector red)
//   g_deg[row] += 1
// ---------------------------------------------------------------------------
__global__ void scatter_kernel(const float* __restrict__ x,
                               const void* __restrict__ eidx_raw,
                               const float* __restrict__ ew,
                               int E, int N) {
    int warp = (int)(((size_t)blockIdx.x * blockDim.x + threadIdx.x) >> 5);
    int lane = threadIdx.x & 31;
    if (warp >= E) return;

    long long row, col;
    if (g_idx_is64) {
        const long long* e64 = (const long long*)eidx_raw;
        row = e64[warp];
        col = e64[(size_t)E + warp];
    } else {
        const int* e32 = (const int*)eidx_raw;
        row = e32[warp];
        col = e32[(size_t)E + warp];
    }
    // Bounds guard: never fault, even if the dtype model is wrong.
    if (row < 0 || row >= N || col < 0 || col >= N) return;

    float w = ew[warp];

    float4 v = *reinterpret_cast<const float4*>(x + (size_t)col * D + lane * 4);
    v.x *= w; v.y *= w; v.z *= w; v.w *= w;

    float* dst = g_agg + (size_t)row * D + lane * 4;
    asm volatile("red.global.add.v4.f32 [%0], {%1,%2,%3,%4};"
                 :: "l"(dst), "f"(v.x), "f"(v.y), "f"(v.z), "f"(v.w)
                 : "memory");
    if (lane == 0) {
        asm volatile("red.global.add.f32 [%0], %1;"
                     :: "l"(g_deg + row), "f"(1.0f) : "memory");
    }
}

// ---------------------------------------------------------------------------
// Kernel 3: fused dual GEMM + epilogue:
//   out[n] = x[n] @ W_lin + g_agg[n] @ W_agg + b_lin + g_deg[n] * b_agg
// Tiling: BM=64 nodes, BN=128 outs, BK=32. 256 threads; each thread owns an
// 8x4 microtile (rows ty*8..+7, cols tx*4..+3).
// ---------------------------------------------------------------------------
__global__ __launch_bounds__(256) void gemm_kernel(
    const float* __restrict__ x,
    const float* __restrict__ Wl, const float* __restrict__ bl,
    const float* __restrict__ Wa, const float* __restrict__ ba,
    float* __restrict__ out, int N)
{
    __shared__ float sX[64][32];
    __shared__ float sA[64][32];
    __shared__ float sWl[32][128];
    __shared__ float sWa[32][128];

    const int tid  = threadIdx.x;
    const int row0 = blockIdx.x * 64;
    const int ty = tid >> 5;   // 0..7  -> row group
    const int tx = tid & 31;   // 0..31 -> col group (x4)

    float acc[8][4];
#pragma unroll
    for (int i = 0; i < 8; i++)
#pragma unroll
        for (int j = 0; j < 4; j++) acc[i][j] = 0.f;

#pragma unroll
    for (int k0 = 0; k0 < 128; k0 += 32) {
        // Load X / agg tiles: 64x32 floats = 512 float4 -> 2 per thread
#pragma unroll
        for (int i = 0; i < 2; i++) {
            int idx = tid + i * 256;
            int r = idx >> 3;
            int c = (idx & 7) << 2;
            int gr = row0 + r;
            float4 vx = make_float4(0.f, 0.f, 0.f, 0.f);
            float4 va = vx;
            if (gr < N) {
                vx = *(const float4*)(x + (size_t)gr * D + k0 + c);
                va = *(const float4*)(g_agg + (size_t)gr * D + k0 + c);
            }
            *(float4*)&sX[r][c] = vx;
            *(float4*)&sA[r][c] = va;
        }
        // Load W tiles: 32x128 floats = 1024 float4 -> 4 per thread
#pragma unroll
        for (int i = 0; i < 4; i++) {
            int idx = tid + i * 256;
            int r = idx >> 5;
            int c = (idx & 31) << 2;
            *(float4*)&sWl[r][c] = *(const float4*)(Wl + (size_t)(k0 + r) * D + c);
            *(float4*)&sWa[r][c] = *(const float4*)(Wa + (size_t)(k0 + r) * D + c);
        }
        __syncthreads();

#pragma unroll
        for (int kk = 0; kk < 32; kk++) {
            float4 wl = *(float4*)&sWl[kk][tx << 2];
            float4 wa = *(float4*)&sWa[kk][tx << 2];
#pragma unroll
            for (int i = 0; i < 8; i++) {
                float xv = sX[(ty << 3) + i][kk];
                float av = sA[(ty << 3) + i][kk];
                acc[i][0] = fmaf(xv, wl.x, fmaf(av, wa.x, acc[i][0]));
                acc[i][1] = fmaf(xv, wl.y, fmaf(av, wa.y, acc[i][1]));
                acc[i][2] = fmaf(xv, wl.z, fmaf(av, wa.z, acc[i][2]));
                acc[i][3] = fmaf(xv, wl.w, fmaf(av, wa.w, acc[i][3]));
            }
        }
        __syncthreads();
    }

    float4 blv = *(const float4*)(bl + (tx << 2));
    float4 bav = *(const float4*)(ba + (tx << 2));
#pragma unroll
    for (int i = 0; i < 8; i++) {
        int gr = row0 + (ty << 3) + i;
        if (gr < N) {
            float d = g_deg[gr];
            float4 o;
            o.x = acc[i][0] + blv.x + d * bav.x;
            o.y = acc[i][1] + blv.y + d * bav.y;
            o.z = acc[i][2] + blv.z + d * bav.z;
            o.w = acc[i][3] + blv.w + d * bav.w;
            *(float4*)(out + (size_t)gr * D + (tx << 2)) = o;
        }
    }
}

// ---------------------------------------------------------------------------
extern "C" void kernel_launch(void* const* d_in, const int* in_sizes, int n_in,
                              void* d_out, int out_size) {
    const float* x    = (const float*)d_in[0];
    const void*  eidx = d_in[1];
    const float* ew   = (const float*)d_in[2];
    const float* Wl   = (const float*)d_in[3];
    const float* bl   = (const float*)d_in[4];
    const float* Wa   = (const float*)d_in[5];
    const float* ba   = (const float*)d_in[6];
    float*       out  = (float*)d_out;

    int N = in_sizes[0] / D;       // 100000
    int E = in_sizes[2];           // 1600000 (edge_weights count)

    probe_kernel<<<1, 32>>>((const int*)eidx, 2 * E);
    zero_kernel<<<2048, 256>>>(N);

    // one warp per edge, 8 warps per block
    int blocks = (E + 7) / 8;
    scatter_kernel<<<blocks, 256>>>(x, eidx, ew, E, N);

    gemm_kernel<<<(N + 63) / 64, 256>>>(x, Wl, bl, Wa, ba, out, N);
}

// round 3
// speedup vs baseline: 2.2354x; 2.2354x over previous
#include <cuda_runtime.h>
#include <cuda_bf16.h>

#define D 128
#define MAX_N 100000
#define MAX_E 1600000

// ---------------------------------------------------------------------------
// Scratch (device globals — no allocation allowed)
// ---------------------------------------------------------------------------
__device__ __align__(128) float g_agg[(size_t)MAX_N * D];   // per-node weighted neighbor sum
__device__ __align__(128) int   g_count[MAX_N];             // in-degree
__device__ __align__(128) int   g_start[MAX_N];             // CSR offsets
__device__ __align__(128) int   g_cursor[MAX_N];            // fill cursors
__device__ __align__(128) long long g_edge[MAX_E];          // packed (col | w<<32) per CSR slot
__device__ int g_total;                                      // CSR allocation counter
__device__ int g_idx_is64;                                   // edge_index dtype flag

// ---------------------------------------------------------------------------
// Kernel 0: probe edge_index dtype (int64 values < 2^31 -> odd words all 0).
// ---------------------------------------------------------------------------
__global__ void probe_kernel(const int* __restrict__ e32, int n_words) {
    if (threadIdx.x == 0) {
        int any = 0;
        for (int i = 1; i < 256 && i < n_words; i += 2) any |= e32[i];
        g_idx_is64 = (any == 0) ? 1 : 0;
    }
}

__device__ __forceinline__ int load_idx(const void* raw, size_t pos) {
    if (g_idx_is64) return (int)((const long long*)raw)[pos];
    return ((const int*)raw)[pos];
}

// ---------------------------------------------------------------------------
// Kernel 1: zero counters (replays reuse them).
// ---------------------------------------------------------------------------
__global__ void zero_kernel(int N) {
    int i = blockIdx.x * blockDim.x + threadIdx.x;
    if (i < N) g_count[i] = 0;
    if (i == 0) g_total = 0;
}

// ---------------------------------------------------------------------------
// Kernel 2: degree histogram.
// ---------------------------------------------------------------------------
__global__ void count_kernel(const void* __restrict__ eidx, int E, int N) {
    int e = blockIdx.x * blockDim.x + threadIdx.x;
    if (e >= E) return;
    int row = load_idx(eidx, e);
    if (row >= 0 && row < N) atomicAdd(&g_count[row], 1);
}

// ---------------------------------------------------------------------------
// Kernel 3: scan-free CSR slot allocation (ranges need not be ordered).
// ---------------------------------------------------------------------------
__global__ void alloc_kernel(int N) {
    int n = blockIdx.x * blockDim.x + threadIdx.x;
    if (n >= N) return;
    int c = g_count[n];
    int s = atomicAdd(&g_total, c);
    g_start[n] = s;
    g_cursor[n] = s;
}

// ---------------------------------------------------------------------------
// Kernel 4: bin edges into CSR slots.
// ---------------------------------------------------------------------------
__global__ void fill_kernel(const void* __restrict__ eidx,
                            const float* __restrict__ ew, int E, int N) {
    int e = blockIdx.x * blockDim.x + threadIdx.x;
    if (e >= E) return;
    int row = load_idx(eidx, e);
    int col = load_idx(eidx, (size_t)E + e);
    if (row < 0 || row >= N || col < 0 || col >= N) return;
    float w = ew[e];
    int pos = atomicAdd(&g_cursor[row], 1);
    g_edge[pos] = ((long long)__float_as_int(w) << 32) | (unsigned int)col;
}

// ---------------------------------------------------------------------------
// Kernel 5: per-node gather-reduce. One warp per node, 4-wide edge batching
// for MLP. Writes g_agg once (no float atomics, no zero pass needed).
// ---------------------------------------------------------------------------
__global__ void aggregate_kernel(const float* __restrict__ x, int N) {
    int node = blockIdx.x * (blockDim.x >> 5) + (threadIdx.x >> 5);
    int lane = threadIdx.x & 31;
    if (node >= N) return;

    int deg  = g_count[node];
    int base = g_start[node];

    float4 acc = make_float4(0.f, 0.f, 0.f, 0.f);
    for (int e0 = 0; e0 < deg; e0 += 4) {
        long long p[4];
        float4 v[4];
        int m = deg - e0; if (m > 4) m = 4;
#pragma unroll
        for (int j = 0; j < 4; j++)
            if (j < m) p[j] = g_edge[base + e0 + j];     // warp-broadcast load
#pragma unroll
        for (int j = 0; j < 4; j++)
            if (j < m) {
                int col = (int)(p[j] & 0xffffffffLL);
                v[j] = *reinterpret_cast<const float4*>(x + (size_t)col * D + lane * 4);
            }
#pragma unroll
        for (int j = 0; j < 4; j++)
            if (j < m) {
                float w = __int_as_float((int)(p[j] >> 32));
                acc.x = fmaf(w, v[j].x, acc.x);
                acc.y = fmaf(w, v[j].y, acc.y);
                acc.z = fmaf(w, v[j].z, acc.z);
                acc.w = fmaf(w, v[j].w, acc.w);
            }
    }
    *reinterpret_cast<float4*>(g_agg + (size_t)node * D + lane * 4) = acc;
}

// ---------------------------------------------------------------------------
// Kernel 6: fused dual GEMM + epilogue.
//   out[n] = x[n]@W_lin + g_agg[n]@W_agg + b_lin + deg[n]*b_agg
// BM=128, BN=128, BK=16, 256 threads, 8x8 microtile with split ownership:
// thread (tx,ty) owns rows {4ty..4ty+3, 64+4ty..} x cols {4tx..4tx+3, 64+4tx..}
// -> all LDS128 patterns are 2-phase (conflict-optimal).
// ---------------------------------------------------------------------------
__global__ __launch_bounds__(256, 2) void gemm_kernel(
    const float* __restrict__ x,
    const float* __restrict__ Wl, const float* __restrict__ bl,
    const float* __restrict__ Wa, const float* __restrict__ ba,
    float* __restrict__ out, int N)
{
    __shared__ float sX[16][132];   // transposed: sX[k][row]
    __shared__ float sA[16][132];
    __shared__ float sWl[16][132];  // natural: sWl[k][col]
    __shared__ float sWa[16][132];

    const int tid = threadIdx.x;
    const int tx = tid & 15;
    const int ty = tid >> 4;
    const int row0 = blockIdx.x * 128;

    float acc[8][8];
#pragma unroll
    for (int i = 0; i < 8; i++)
#pragma unroll
        for (int j = 0; j < 8; j++) acc[i][j] = 0.f;

#pragma unroll 1
    for (int k0 = 0; k0 < 128; k0 += 16) {
        // X / A tiles (128 rows x 16 k), stored transposed. 512 float4 loads.
#pragma unroll
        for (int t = 0; t < 2; t++) {
            int idx = tid + t * 256;
            int r  = idx >> 2;          // 0..127
            int kq = (idx & 3) << 2;    // 0,4,8,12
            int gr = row0 + r;
            float4 vx = make_float4(0.f, 0.f, 0.f, 0.f);
            float4 va = vx;
            if (gr < N) {
                vx = *(const float4*)(x     + (size_t)gr * D + k0 + kq);
                va = *(const float4*)(g_agg + (size_t)gr * D + k0 + kq);
            }
            sX[kq + 0][r] = vx.x; sX[kq + 1][r] = vx.y;
            sX[kq + 2][r] = vx.z; sX[kq + 3][r] = vx.w;
            sA[kq + 0][r] = va.x; sA[kq + 1][r] = va.y;
            sA[kq + 2][r] = va.z; sA[kq + 3][r] = va.w;
        }
        // Weight tiles (16 k x 128 cols). 512 float4 loads each pair.
#pragma unroll
        for (int t = 0; t < 2; t++) {
            int idx = tid + t * 256;
            int r = idx >> 5;            // 0..15
            int c = (idx & 31) << 2;     // 0..124
            *(float4*)&sWl[r][c] = *(const float4*)(Wl + (size_t)(k0 + r) * D + c);
            *(float4*)&sWa[r][c] = *(const float4*)(Wa + (size_t)(k0 + r) * D + c);
        }
        __syncthreads();

#pragma unroll
        for (int kk = 0; kk < 16; kk++) {
            float xv[8], av[8], wl[8], wa[8];
            *(float4*)&xv[0] = *(float4*)&sX[kk][4 * ty];
            *(float4*)&xv[4] = *(float4*)&sX[kk][64 + 4 * ty];
            *(float4*)&av[0] = *(float4*)&sA[kk][4 * ty];
            *(float4*)&av[4] = *(float4*)&sA[kk][64 + 4 * ty];
            *(float4*)&wl[0] = *(float4*)&sWl[kk][4 * tx];
            *(float4*)&wl[4] = *(float4*)&sWl[kk][64 + 4 * tx];
            *(float4*)&wa[0] = *(float4*)&sWa[kk][4 * tx];
            *(float4*)&wa[4] = *(float4*)&sWa[kk][64 + 4 * tx];
#pragma unroll
            for (int i = 0; i < 8; i++)
#pragma unroll
                for (int j = 0; j < 8; j++)
                    acc[i][j] = fmaf(xv[i], wl[j], fmaf(av[i], wa[j], acc[i][j]));
        }
        __syncthreads();
    }

    // Epilogue
    float4 bl0 = *(const float4*)(bl + 4 * tx);
    float4 bl1 = *(const float4*)(bl + 64 + 4 * tx);
    float4 ba0 = *(const float4*)(ba + 4 * tx);
    float4 ba1 = *(const float4*)(ba + 64 + 4 * tx);

#pragma unroll
    for (int i = 0; i < 8; i++) {
        int r = (i < 4) ? (4 * ty + i) : (64 + 4 * ty + i - 4);
        int gr = row0 + r;
        if (gr >= N) continue;
        float d = (float)g_count[gr];
        float4 o0, o1;
        o0.x = acc[i][0] + bl0.x + d * ba0.x;
        o0.y = acc[i][1] + bl0.y + d * ba0.y;
        o0.z = acc[i][2] + bl0.z + d * ba0.z;
        o0.w = acc[i][3] + bl0.w + d * ba0.w;
        o1.x = acc[i][4] + bl1.x + d * ba1.x;
        o1.y = acc[i][5] + bl1.y + d * ba1.y;
        o1.z = acc[i][6] + bl1.z + d * ba1.z;
        o1.w = acc[i][7] + bl1.w + d * ba1.w;
        *(float4*)(out + (size_t)gr * D + 4 * tx)      = o0;
        *(float4*)(out + (size_t)gr * D + 64 + 4 * tx) = o1;
    }
}

// ---------------------------------------------------------------------------
extern "C" void kernel_launch(void* const* d_in, const int* in_sizes, int n_in,
                              void* d_out, int out_size) {
    const float* x    = (const float*)d_in[0];
    const void*  eidx = d_in[1];
    const float* ew   = (const float*)d_in[2];
    const float* Wl   = (const float*)d_in[3];
    const float* bl   = (const float*)d_in[4];
    const float* Wa   = (const float*)d_in[5];
    const float* ba   = (const float*)d_in[6];
    float*       out  = (float*)d_out;

    int N = in_sizes[0] / D;   // 100000
    int E = in_sizes[2];       // 1600000

    probe_kernel<<<1, 32>>>((const int*)eidx, 2 * E);
    zero_kernel<<<(N + 255) / 256, 256>>>(N);
    count_kernel<<<(E + 255) / 256, 256>>>(eidx, E, N);
    alloc_kernel<<<(N + 255) / 256, 256>>>(N);
    fill_kernel<<<(E + 255) / 256, 256>>>(eidx, ew, E, N);
    aggregate_kernel<<<(N + 7) / 8, 256>>>(x, N);       // one warp per node
    gemm_kernel<<<(N + 127) / 128, 256>>>(x, Wl, bl, Wa, ba, out, N);
}

// round 7
// speedup vs baseline: 2.9408x; 1.3156x over previous
#include <cuda_runtime.h>
#include <cuda_bf16.h>
#include <cstdint>

#define D 128
#define MAX_N 100000
#define MAX_E 1600000

// ---------------------------------------------------------------------------
// Scratch (device globals — no allocation allowed)
// ---------------------------------------------------------------------------
__device__ __align__(128) float g_agg[(size_t)MAX_N * D];   // per-node weighted neighbor sum
__device__ __align__(128) int   g_count[MAX_N];             // in-degree
__device__ __align__(128) int   g_start[MAX_N];             // CSR offsets
__device__ __align__(128) int   g_cursor[MAX_N];            // fill cursors
__device__ __align__(128) long long g_edge[MAX_E];          // packed (w<<32 | col)
// Precomputed B fragments for mma.sync.m16n8k16 (row.col, bf16):
// index [(kstep*16 + ntile)*32 + lane] -> {b0_hi, b1_hi, b0_lo, b1_lo}
__device__ __align__(128) uint4 g_Bfrag[16 * 16 * 32];
__device__ int g_total;
__device__ int g_idx_is64;

// ---------------------------------------------------------------------------
// Helpers
// ---------------------------------------------------------------------------
__device__ __forceinline__ uint32_t smem_u32(const void* p) {
    uint32_t a;
    asm("{ .reg .u64 t; cvta.to.shared.u64 t, %1; cvt.u32.u64 %0, t; }" : "=r"(a) : "l"(p));
    return a;
}
__device__ __forceinline__ uint32_t bf16_bits(float f) {
    return (uint32_t)__bfloat16_as_ushort(__float2bfloat16(f));
}
__device__ __forceinline__ float bf16_val(float f) {
    return __bfloat162float(__float2bfloat16(f));
}
__device__ __forceinline__ uint32_t pack_bf16(float lo_elem, float hi_elem) {
    // low 16 bits = element with smaller k
    return bf16_bits(lo_elem) | (bf16_bits(hi_elem) << 16);
}
__device__ __forceinline__ void mma_bf16(float* c, const uint32_t* a,
                                         uint32_t b0, uint32_t b1) {
    asm volatile(
        "mma.sync.aligned.m16n8k16.row.col.f32.bf16.bf16.f32 "
        "{%0,%1,%2,%3}, {%4,%5,%6,%7}, {%8,%9}, {%0,%1,%2,%3};"
        : "+f"(c[0]), "+f"(c[1]), "+f"(c[2]), "+f"(c[3])
        : "r"(a[0]), "r"(a[1]), "r"(a[2]), "r"(a[3]), "r"(b0), "r"(b1));
}
__device__ __forceinline__ void ldmatrix_x4(uint32_t* r, uint32_t addr) {
    asm volatile("ldmatrix.sync.aligned.m8n8.x4.shared.b16 {%0,%1,%2,%3}, [%4];"
                 : "=r"(r[0]), "=r"(r[1]), "=r"(r[2]), "=r"(r[3]) : "r"(addr));
}

// ---------------------------------------------------------------------------
// Kernel 0: probe edge_index dtype.
// ---------------------------------------------------------------------------
__global__ void probe_kernel(const int* __restrict__ e32, int n_words) {
    if (threadIdx.x == 0) {
        int any = 0;
        for (int i = 1; i < 256 && i < n_words; i += 2) any |= e32[i];
        g_idx_is64 = (any == 0) ? 1 : 0;
    }
}
__device__ __forceinline__ int load_idx(const void* raw, size_t pos) {
    if (g_idx_is64) return (int)((const long long*)raw)[pos];
    return ((const int*)raw)[pos];
}

// ---------------------------------------------------------------------------
// Kernel 1: zero counters.
// ---------------------------------------------------------------------------
__global__ void zero_kernel(int N) {
    int i = blockIdx.x * blockDim.x + threadIdx.x;
    if (i < N) g_count[i] = 0;
    if (i == 0) g_total = 0;
}

// ---------------------------------------------------------------------------
// Kernel 2: degree histogram.
// ---------------------------------------------------------------------------
__global__ void count_kernel(const void* __restrict__ eidx, int E, int N) {
    int e = blockIdx.x * blockDim.x + threadIdx.x;
    if (e >= E) return;
    int row = load_idx(eidx, e);
    if (row >= 0 && row < N) atomicAdd(&g_count[row], 1);
}

// ---------------------------------------------------------------------------
// Kernel 3: scan-free CSR slot allocation.
// ---------------------------------------------------------------------------
__global__ void alloc_kernel(int N) {
    int n = blockIdx.x * blockDim.x + threadIdx.x;
    if (n >= N) return;
    int c = g_count[n];
    int s = atomicAdd(&g_total, c);
    g_start[n] = s;
    g_cursor[n] = s;
}

// ---------------------------------------------------------------------------
// Kernel 4: bin edges into CSR slots.
// ---------------------------------------------------------------------------
__global__ void fill_kernel(const void* __restrict__ eidx,
                            const float* __restrict__ ew, int E, int N) {
    int e = blockIdx.x * blockDim.x + threadIdx.x;
    if (e >= E) return;
    int row = load_idx(eidx, e);
    int col = load_idx(eidx, (size_t)E + e);
    if (row < 0 || row >= N || col < 0 || col >= N) return;
    float w = ew[e];
    int pos = atomicAdd(&g_cursor[row], 1);
    g_edge[pos] = ((long long)__float_as_int(w) << 32) | (unsigned int)col;
}

// ---------------------------------------------------------------------------
// Kernel 5: per-node gather-reduce (one warp per node, 4-wide MLP).
// ---------------------------------------------------------------------------
__global__ void aggregate_kernel(const float* __restrict__ x, int N) {
    int node = blockIdx.x * (blockDim.x >> 5) + (threadIdx.x >> 5);
    int lane = threadIdx.x & 31;
    if (node >= N) return;

    int deg  = g_count[node];
    int base = g_start[node];

    float4 acc = make_float4(0.f, 0.f, 0.f, 0.f);
    for (int e0 = 0; e0 < deg; e0 += 4) {
        long long p[4];
        float4 v[4];
        int m = deg - e0; if (m > 4) m = 4;
#pragma unroll
        for (int j = 0; j < 4; j++)
            if (j < m) p[j] = g_edge[base + e0 + j];
#pragma unroll
        for (int j = 0; j < 4; j++)
            if (j < m) {
                int col = (int)(p[j] & 0xffffffffLL);
                v[j] = *reinterpret_cast<const float4*>(x + (size_t)col * D + lane * 4);
            }
#pragma unroll
        for (int j = 0; j < 4; j++)
            if (j < m) {
                float w = __int_as_float((int)(p[j] >> 32));
                acc.x = fmaf(w, v[j].x, acc.x);
                acc.y = fmaf(w, v[j].y, acc.y);
                acc.z = fmaf(w, v[j].z, acc.z);
                acc.w = fmaf(w, v[j].w, acc.w);
            }
    }
    *reinterpret_cast<float4*>(g_agg + (size_t)node * D + lane * 4) = acc;
}

// ---------------------------------------------------------------------------
// Kernel 5b: precompute B fragments. Wcat = [Wl ; Wa] (K=256 x N=128).
// For mma.sync m16n8k16 .row.col, B frag per lane: b0 covers k = k0,k0+1;
// b1 covers k0+8,k0+9 with k0 = kstep*16 + (lane%4)*2, n = ntile*8 + lane/4.
// ---------------------------------------------------------------------------
__global__ void prep_w_kernel(const float* __restrict__ Wl,
                              const float* __restrict__ Wa) {
    int id = blockIdx.x * blockDim.x + threadIdx.x;
    if (id >= 16 * 16 * 32) return;
    int lane = id & 31;
    int t    = (id >> 5) & 15;   // ntile
    int s    = id >> 9;          // kstep
    int n  = t * 8 + (lane >> 2);
    int k0 = s * 16 + ((lane & 3) << 1);

    float a[4];
#pragma unroll
    for (int j = 0; j < 4; j++) {
        int k = k0 + ((j >> 1) << 3) + (j & 1);   // k0, k0+1, k0+8, k0+9
        a[j] = (k < 128) ? Wl[k * 128 + n] : Wa[(k - 128) * 128 + n];
    }
    uint4 v;
    v.x = pack_bf16(a[0], a[1]);                       // b0 hi
    v.y = pack_bf16(a[2], a[3]);                       // b1 hi
    v.z = pack_bf16(a[0] - bf16_val(a[0]), a[1] - bf16_val(a[1]));  // b0 lo
    v.w = pack_bf16(a[2] - bf16_val(a[2]), a[3] - bf16_val(a[3]));  // b1 lo
    g_Bfrag[id] = v;
}

// ---------------------------------------------------------------------------
// Kernel 6: fused GEMM via legacy mma.sync, 3xBF16 error-compensated:
//   out[m] = [x[m] | agg[m]] @ [Wl ; Wa] + b_lin + deg[m]*b_agg
// BM=128, BN=128, K=256 in 16 steps of k16. 8 warps in 4(M) x 2(N):
// warp tile 32x64 = 2 m16-tiles x 8 n8-tiles, fp32 accum (64 regs).
// A staged f32 -> bf16 hi/lo in smem (row pitch 24 halves = 48B:
// conflict-free for both STS and ldmatrix), double-buffered.
// ---------------------------------------------------------------------------
__global__ __launch_bounds__(256) void gemm_mma_kernel(
    const float* __restrict__ x,
    const float* __restrict__ bl, const float* __restrict__ ba,
    float* __restrict__ out, int N)
{
    __shared__ uint32_t sAhi[2][128 * 12];   // 128 rows x 24 halves (16 used)
    __shared__ uint32_t sAlo[2][128 * 12];

    const int tid  = threadIdx.x;
    const int wid  = tid >> 5;
    const int lane = tid & 31;
    const int row0 = blockIdx.x * 128;
    const int warpM = wid & 3;     // 0..3 -> rows warpM*32
    const int warpN = wid >> 2;    // 0..1 -> cols warpN*64

    float acc[2][8][4];
#pragma unroll
    for (int m = 0; m < 2; m++)
#pragma unroll
        for (int n = 0; n < 8; n++)
#pragma unroll
            for (int j = 0; j < 4; j++) acc[m][n][j] = 0.f;

    const uint32_t hi_base0 = smem_u32(&sAhi[0][0]);
    const uint32_t lo_base0 = smem_u32(&sAlo[0][0]);

    // staging lambda-ish via macro-free inline: stage step s into buffer b
    auto stage = [&](int s, int b) {
        const float* src = (s < 8) ? x : g_agg;
        int koff = (s & 7) * 16;
#pragma unroll
        for (int i = 0; i < 2; i++) {
            int idx = tid + i * 256;
            int r   = idx >> 2;
            int c4  = (idx & 3) << 2;
            int gr  = row0 + r;
            float4 v = make_float4(0.f, 0.f, 0.f, 0.f);
            if (gr < N) v = *(const float4*)(src + (size_t)gr * D + koff + c4);
            uint32_t h0 = pack_bf16(v.x, v.y);
            uint32_t h1 = pack_bf16(v.z, v.w);
            uint32_t l0 = pack_bf16(v.x - bf16_val(v.x), v.y - bf16_val(v.y));
            uint32_t l1 = pack_bf16(v.z - bf16_val(v.z), v.w - bf16_val(v.w));
            int o = r * 12 + (c4 >> 1);
            sAhi[b][o] = h0; sAhi[b][o + 1] = h1;
            sAlo[b][o] = l0; sAlo[b][o + 1] = l1;
        }
    };

    stage(0, 0);
    __syncthreads();

#pragma unroll 1
    for (int s = 0; s < 16; s++) {
        int b = s & 1;
        if (s < 15) stage(s + 1, b ^ 1);

        // B fragments for this k-step (L1-resident after first CTA on the SM)
        uint4 bf[8];
#pragma unroll
        for (int n = 0; n < 8; n++)
            bf[n] = __ldg(&g_Bfrag[((s * 16) + warpN * 8 + n) * 32 + lane]);

        // A fragments via ldmatrix
        uint32_t ahi[2][4], alo[2][4];
        uint32_t lane_off = (uint32_t)(lane & 15) * 48 + ((lane >> 4) << 4);
        uint32_t buf_off  = (uint32_t)b * (128 * 12 * 4);
#pragma unroll
        for (int m = 0; m < 2; m++) {
            uint32_t rowb = (uint32_t)(warpM * 32 + m * 16) * 48;
            ldmatrix_x4(ahi[m], hi_base0 + buf_off + rowb + lane_off);
            ldmatrix_x4(alo[m], lo_base0 + buf_off + rowb + lane_off);
        }

#pragma unroll
        for (int m = 0; m < 2; m++)
#pragma unroll
            for (int n = 0; n < 8; n++) {
                mma_bf16(acc[m][n], ahi[m], bf[n].x, bf[n].y);   // Ahi*Bhi
                mma_bf16(acc[m][n], ahi[m], bf[n].z, bf[n].w);   // Ahi*Blo
                mma_bf16(acc[m][n], alo[m], bf[n].x, bf[n].y);   // Alo*Bhi
            }
        __syncthreads();
    }

    // ---- epilogue ----
    int rbase = row0 + warpM * 32 + (lane >> 2);
#pragma unroll
    for (int m = 0; m < 2; m++) {
        int r_lo = rbase + m * 16;
        int r_hi = r_lo + 8;
        float d_lo = (r_lo < N) ? (float)g_count[r_lo] : 0.f;
        float d_hi = (r_hi < N) ? (float)g_count[r_hi] : 0.f;
#pragma unroll
        for (int n = 0; n < 8; n++) {
            int c = warpN * 64 + n * 8 + ((lane & 3) << 1);
            float2 b1 = *(const float2*)(bl + c);
            float2 b2 = *(const float2*)(ba + c);
            if (r_lo < N) {
                float2 o;
                o.x = acc[m][n][0] + b1.x + d_lo * b2.x;
                o.y = acc[m][n][1] + b1.y + d_lo * b2.y;
                *(float2*)(out + (size_t)r_lo * D + c) = o;
            }
            if (r_hi < N) {
                float2 o;
                o.x = acc[m][n][2] + b1.x + d_hi * b2.x;
                o.y = acc[m][n][3] + b1.y + d_hi * b2.y;
                *(float2*)(out + (size_t)r_hi * D + c) = o;
            }
        }
    }
}

// ---------------------------------------------------------------------------
extern "C" void kernel_launch(void* const* d_in, const int* in_sizes, int n_in,
                              void* d_out, int out_size) {
    const float* x    = (const float*)d_in[0];
    const void*  eidx = d_in[1];
    const float* ew   = (const float*)d_in[2];
    const float* Wl   = (const float*)d_in[3];
    const float* bl   = (const float*)d_in[4];
    const float* Wa   = (const float*)d_in[5];
    const float* ba   = (const float*)d_in[6];
    float*       out  = (float*)d_out;

    int N = in_sizes[0] / D;   // 100000
    int E = in_sizes[2];       // 1600000

    probe_kernel<<<1, 32>>>((const int*)eidx, 2 * E);
    zero_kernel<<<(N + 255) / 256, 256>>>(N);
    prep_w_kernel<<<32, 256>>>(Wl, Wa);
    count_kernel<<<(E + 255) / 256, 256>>>(eidx, E, N);
    alloc_kernel<<<(N + 255) / 256, 256>>>(N);
    fill_kernel<<<(E + 255) / 256, 256>>>(eidx, ew, E, N);
    aggregate_kernel<<<(N + 7) / 8, 256>>>(x, N);
    gemm_mma_kernel<<<(N + 127) / 128, 256>>>(x, bl, ba, out, N);
}